// round 14
// baseline (speedup 1.0000x reference)
#include <cuda_runtime.h>
#include <cuda_bf16.h>
#include <cstdint>

// ============================ Problem constants ============================
#define VTAGS 50257
#define BATCH 2048
#define EMB   128
#define NCTX  10
#define KDIM  384
#define CTXROWS (BATCH * NCTX)     // 20480
#define NT      4                  // n-tiles per CTA in tag GEMM
#define NGROUPS 99                 // ceil(393 / NT)

// ============================ Scratch (device globals) =====================
__device__ __nv_bfloat16 g_v_bf16[BATCH * EMB];            // pooled vectors
__device__ __nv_bfloat16 g_tag_bf16[VTAGS * EMB];          // tag embedding bf16
__device__ __nv_bfloat16 g_ctx_bf16[CTXROWS * KDIM];       // gathered contexts
__device__ __nv_bfloat16 g_Wt_bf16[EMB * KDIM];            // W_fc transposed [e][k]
__device__ __nv_bfloat16 g_ct_bf16[CTXROWS * EMB];         // c_tilde bf16
__device__ float g_partials[NGROUPS * BATCH];
__device__ float g_inv_sum[BATCH];

// ============================ helpers ======================================
__device__ __forceinline__ uint32_t smem_to_u32(const void* smem_ptr) {
    uint32_t addr;
    asm("{ .reg .u64 tmp; cvta.to.shared.u64 tmp, %1; cvt.u32.u64 %0, tmp; }"
        : "=r"(addr) : "l"(smem_ptr));
    return addr;
}

__device__ __forceinline__ void stg_cs(float* p, float v) {
    asm volatile("st.global.cs.f32 [%0], %1;" :: "l"(p), "f"(v) : "memory");
}
__device__ __forceinline__ void stg_cs4(float* p, float4 v) {
    asm volatile("st.global.cs.v4.f32 [%0], {%1,%2,%3,%4};"
                 :: "l"(p), "f"(v.x), "f"(v.y), "f"(v.z), "f"(v.w) : "memory");
}

__device__ __forceinline__ void cp_async16(uint32_t dst, const void* src) {
    asm volatile("cp.async.cg.shared.global [%0], [%1], 16;"
                 :: "r"(dst), "l"(src) : "memory");
}
__device__ __forceinline__ void cp_commit() {
    asm volatile("cp.async.commit_group;" ::: "memory");
}
__device__ __forceinline__ void cp_wait1() {
    asm volatile("cp.async.wait_group 1;" ::: "memory");
}
__device__ __forceinline__ void cp_wait0() {
    asm volatile("cp.async.wait_group 0;" ::: "memory");
}

#define LDMATRIX_X4(r, addr) \
    asm volatile("ldmatrix.sync.aligned.m8n8.x4.shared.b16 {%0,%1,%2,%3}, [%4];" \
        : "=r"((r)[0]), "=r"((r)[1]), "=r"((r)[2]), "=r"((r)[3]) : "r"(addr))

#define MMA_BF16(d, a, b) \
    asm volatile("mma.sync.aligned.m16n8k16.row.col.f32.bf16.bf16.f32 " \
        "{%0,%1,%2,%3}, {%4,%5,%6,%7}, {%8,%9}, {%0,%1,%2,%3};" \
        : "+f"((d)[0]), "+f"((d)[1]), "+f"((d)[2]), "+f"((d)[3]) \
        : "r"((a)[0]), "r"((a)[1]), "r"((a)[2]), "r"((a)[3]), \
          "r"((b)[0]), "r"((b)[1]))

#define SA_STRIDE 272

// ===================== K1a: gather contexts + W^T + tag convert ============
__global__ void __launch_bounds__(128)
gather_kernel(const int* __restrict__ v1i, const int* __restrict__ pthi,
              const int* __restrict__ v2i,
              const float* __restrict__ vemb, const float* __restrict__ pemb,
              const float* __restrict__ tag,  const float* __restrict__ Wfc)
{
    int b = blockIdx.x, tid = threadIdx.x;

    #pragma unroll
    for (int n = 0; n < NCTX; n++) {
        int i1 = v1i[b * NCTX + n];
        int ip = pthi[b * NCTX + n];
        int i2 = v2i[b * NCTX + n];
        size_t ro = (size_t)(b * NCTX + n) * KDIM;
        g_ctx_bf16[ro + tid]       = __float2bfloat16(vemb[(size_t)i1 * EMB + tid]);
        g_ctx_bf16[ro + 128 + tid] = __float2bfloat16(pemb[(size_t)ip * EMB + tid]);
        g_ctx_bf16[ro + 256 + tid] = __float2bfloat16(vemb[(size_t)i2 * EMB + tid]);
    }

    // W transpose: W[k][e] -> g_Wt[e][k]  (first 384 blocks, 1 elem/thread)
    int g = b * 128 + tid;
    if (g < KDIM * EMB) {
        int k = g >> 7, e = g & 127;
        g_Wt_bf16[e * KDIM + k] = __float2bfloat16(Wfc[g]);
    }

    // tag f32 -> bf16, grid-stride
    const int n4 = (VTAGS * EMB) / 4;
    const int nth = BATCH * 128;
    for (int i = b * 128 + tid; i < n4; i += nth) {
        float4 v = reinterpret_cast<const float4*>(tag)[i];
        __nv_bfloat162 a2, b2;
        a2.x = __float2bfloat16(v.x); a2.y = __float2bfloat16(v.y);
        b2.x = __float2bfloat16(v.z); b2.y = __float2bfloat16(v.w);
        uint2 u;
        u.x = *reinterpret_cast<uint32_t*>(&a2);
        u.y = *reinterpret_cast<uint32_t*>(&b2);
        reinterpret_cast<uint2*>(g_tag_bf16)[i] = u;
    }
}

// ===================== K1b: FC GEMM (ctx @ W + b, tanh) via HMMA ===========
// 160 CTAs x 256 thr; tile 128 rows x 128 cols x K=384 (3 chunks in smem).
#define FC_CHUNK 34816
#define SMEM_FC_TOTAL (6 * FC_CHUNK)    // 208896

__global__ void __launch_bounds__(256, 1)
fc_kernel(const float* __restrict__ bfc)
{
    extern __shared__ __align__(16) char smem[];
    const int tid  = threadIdx.x;
    const int lane = tid & 31;
    const int wid  = tid >> 5;
    const int warp_m = wid & 3;
    const int warp_n = wid >> 2;
    const int m0 = blockIdx.x * 128;
    const uint32_t su = smem_to_u32(smem);

    // Stage A (3 chunks) + Wt (3 chunks)
    #pragma unroll
    for (int c = 0; c < 3; c++) {
        uint32_t ab = su + c * FC_CHUNK;
        uint32_t wb = su + (3 + c) * FC_CHUNK;
        #pragma unroll
        for (int i = 0; i < 8; i++) {
            int j = tid + i * 256;
            int row = j >> 4, c16 = j & 15;
            cp_async16(ab + row * SA_STRIDE + c16 * 16,
                       g_ctx_bf16 + (size_t)(m0 + row) * KDIM + c * 128 + c16 * 8);
            cp_async16(wb + row * SA_STRIDE + c16 * 16,
                       g_Wt_bf16 + (size_t)row * KDIM + c * 128 + c16 * 8);
        }
    }
    cp_commit(); cp_wait0();
    __syncthreads();

    float acc[2][8][4];
    #pragma unroll
    for (int mi = 0; mi < 2; mi++)
        #pragma unroll
        for (int ni = 0; ni < 8; ni++)
            #pragma unroll
            for (int j = 0; j < 4; j++) acc[mi][ni][j] = 0.0f;

    const uint32_t aoff = (warp_m * 32 + (lane & 15)) * SA_STRIDE + (lane >> 4) * 16;
    const uint32_t boff = (warp_n * 64 + (lane & 7) + ((lane >> 4) & 1) * 8) * SA_STRIDE
                        + ((lane >> 3) & 1) * 16;

    #pragma unroll
    for (int c = 0; c < 3; c++) {
        const uint32_t aA = su + c * FC_CHUNK + aoff;
        const uint32_t bA = su + (3 + c) * FC_CHUNK + boff;
        #pragma unroll
        for (int ks = 0; ks < 8; ks++) {
            uint32_t a0[4], a1[4];
            LDMATRIX_X4(a0, aA + ks * 32);
            LDMATRIX_X4(a1, aA + 16 * SA_STRIDE + ks * 32);
            uint32_t b[8][2];
            #pragma unroll
            for (int nb = 0; nb < 4; nb++) {
                uint32_t r[4];
                LDMATRIX_X4(r, bA + nb * 16 * SA_STRIDE + ks * 32);
                b[2 * nb][0]     = r[0]; b[2 * nb][1]     = r[1];
                b[2 * nb + 1][0] = r[2]; b[2 * nb + 1][1] = r[3];
            }
            #pragma unroll
            for (int ni = 0; ni < 8; ni++) {
                MMA_BF16(acc[0][ni], a0, b[ni]);
                MMA_BF16(acc[1][ni], a1, b[ni]);
            }
        }
    }

    // Epilogue: tanh(acc + b_fc) -> bf16
    const int r0 = warp_m * 32 + (lane >> 2);
    #pragma unroll
    for (int ni = 0; ni < 8; ni++) {
        int nb = warp_n * 64 + ni * 8 + 2 * (lane & 3);
        float b0 = bfc[nb], b1 = bfc[nb + 1];
        #pragma unroll
        for (int k = 0; k < 4; k++) {
            int mi = k >> 1, jo = (k & 1) * 2;
            int m = m0 + r0 + 8 * k;
            float t0 = tanhf(acc[mi][ni][jo + 0] + b0);
            float t1 = tanhf(acc[mi][ni][jo + 1] + b1);
            __nv_bfloat162 p;
            p.x = __float2bfloat16(t0); p.y = __float2bfloat16(t1);
            *reinterpret_cast<__nv_bfloat162*>(g_ct_bf16 + (size_t)m * EMB + nb) = p;
        }
    }
}

// ===================== K1c: attention pooling per function =================
__global__ void __launch_bounds__(128)
attention_kernel(const float* __restrict__ watt, const float* __restrict__ batt)
{
    __shared__ float cts[NCTX * EMB];
    __shared__ float s_logit[NCTX];
    int b = blockIdx.x, tid = threadIdx.x;
    int wid = tid >> 5, lid = tid & 31;

    float c[NCTX];
    #pragma unroll
    for (int n = 0; n < NCTX; n++)
        c[n] = __bfloat162float(g_ct_bf16[(size_t)(b * NCTX + n) * EMB + tid]);

    float wa = watt[tid];
    #pragma unroll
    for (int n = 0; n < NCTX; n++) cts[n * EMB + tid] = c[n] * wa;
    __syncthreads();
    for (int n = wid; n < NCTX; n += 4) {
        float p = cts[n * EMB + lid] + cts[n * EMB + lid + 32]
                + cts[n * EMB + lid + 64] + cts[n * EMB + lid + 96];
        #pragma unroll
        for (int o = 16; o > 0; o >>= 1) p += __shfl_xor_sync(0xFFFFFFFFu, p, o);
        if (lid == 0) s_logit[n] = p;
    }
    __syncthreads();

    float ba = batt[0];
    float sl[NCTX], mx = -1e30f;
    #pragma unroll
    for (int n = 0; n < NCTX; n++) { sl[n] = s_logit[n] + ba; mx = fmaxf(mx, sl[n]); }
    float ssum = 0.0f;
    #pragma unroll
    for (int n = 0; n < NCTX; n++) { sl[n] = expf(sl[n] - mx); ssum += sl[n]; }
    float rs = 1.0f / ssum;

    float vout = 0.0f;
    #pragma unroll
    for (int n = 0; n < NCTX; n++) vout = fmaf(c[n], sl[n] * rs, vout);
    g_v_bf16[b * EMB + tid] = __float2bfloat16(vout);
}

// ===================== K3: HMMA tag GEMM + softmax, NT tiles per CTA =======
#define SMEM_A_OFF   0
#define SMEM_B_OFF   34816
#define SMEM_B_BYTES 34816
#define SMEM_RED_OFF (SMEM_B_OFF + 2 * SMEM_B_BYTES)
#define SMEM_K3_TOTAL (SMEM_RED_OFF + 1024)
#define STG_STRIDE 132          // stage floats per row (conflict-free LDS.128)

template<bool WRITE>
__global__ void __launch_bounds__(256, 2)
gemm_softmax_kernel(float* __restrict__ out)
{
    extern __shared__ __align__(16) char smem[];

    const int tid  = threadIdx.x;
    const int lane = tid & 31;
    const int wid  = tid >> 5;
    const int warp_m = wid & 3;
    const int warp_n = wid >> 2;
    const int group_n0 = blockIdx.x * (NT * 128);
    const int tile_m0 = blockIdx.y * 128;

    const uint32_t smem_u = smem_to_u32(smem);
    const uint32_t sAu = smem_u + SMEM_A_OFF;

    const uint4* gA = reinterpret_cast<const uint4*>(g_v_bf16 + (size_t)tile_m0 * EMB);
    #pragma unroll
    for (int i = 0; i < 8; i++) {
        int j = tid + i * 256;
        int row = j >> 4, c = j & 15;
        *reinterpret_cast<uint4*>(smem + SMEM_A_OFF + row * SA_STRIDE + c * 16) = gA[j];
    }

    auto issueB = [&](int t, int buf) {
        int n0 = group_n0 + t * 128;
        uint32_t base = smem_u + SMEM_B_OFF + buf * SMEM_B_BYTES;
        #pragma unroll
        for (int i = 0; i < 8; i++) {
            int j = tid + i * 256;
            int row = j >> 4, c16 = j & 15;
            int gr = n0 + row; if (gr > VTAGS - 1) gr = VTAGS - 1;
            cp_async16(base + row * SA_STRIDE + c16 * 16,
                       g_tag_bf16 + (size_t)gr * EMB + c16 * 8);
        }
        cp_commit();
    };
    issueB(0, 0);

    const uint32_t aAddr0 = sAu + (warp_m * 32 + (lane & 15)) * SA_STRIDE
                                + (lane >> 4) * 16;
    const uint32_t aAddr1 = aAddr0 + 16 * SA_STRIDE;
    const uint32_t bOff = (warp_n * 64 + (lane & 7) + ((lane >> 4) & 1) * 8) * SA_STRIDE
                        + ((lane >> 3) & 1) * 16;

    const int r0 = warp_m * 32 + (lane >> 2);
    float ssum[4] = {0.0f, 0.0f, 0.0f, 0.0f};
    float inv[4];
    if (WRITE) {
        #pragma unroll
        for (int k = 0; k < 4; k++)
            inv[k] = g_inv_sum[tile_m0 + r0 + k * 8];
    }
    // store-alignment phases (constant per thread; row&3 == wid&3 for rows it*8+wid)
    const int hr = (4 - ((lane >> 2) & 3)) & 3;   // staging rotation for my values
    const int hm = (4 - (wid & 3)) & 3;           // store shift for my rows

    for (int t = 0; t < NT; t++) {
        const int buf = t & 1;
        const uint32_t sBu = smem_u + SMEM_B_OFF + buf * SMEM_B_BYTES;
        if (t + 1 < NT) { issueB(t + 1, buf ^ 1); cp_wait1(); }
        else           { cp_wait0(); }
        __syncthreads();

        float acc[2][8][4];
        #pragma unroll
        for (int mi = 0; mi < 2; mi++)
            #pragma unroll
            for (int ni = 0; ni < 8; ni++)
                #pragma unroll
                for (int j = 0; j < 4; j++) acc[mi][ni][j] = 0.0f;

        const uint32_t bAddr = sBu + bOff;
        #pragma unroll
        for (int ks = 0; ks < 8; ks++) {
            uint32_t a0[4], a1[4];
            LDMATRIX_X4(a0, aAddr0 + ks * 32);
            LDMATRIX_X4(a1, aAddr1 + ks * 32);
            uint32_t b[8][2];
            #pragma unroll
            for (int nb = 0; nb < 4; nb++) {
                uint32_t r[4];
                LDMATRIX_X4(r, bAddr + nb * 16 * SA_STRIDE + ks * 32);
                b[2 * nb][0]     = r[0]; b[2 * nb][1]     = r[1];
                b[2 * nb + 1][0] = r[2]; b[2 * nb + 1][1] = r[3];
            }
            #pragma unroll
            for (int ni = 0; ni < 8; ni++) {
                MMA_BF16(acc[0][ni], a0, b[ni]);
                MMA_BF16(acc[1][ni], a1, b[ni]);
            }
        }
        __syncthreads();

        const int tile_n0 = group_n0 + t * 128;
        const bool tail = (tile_n0 + 128 > VTAGS);

        if (!WRITE) {
            #pragma unroll
            for (int ni = 0; ni < 8; ni++) {
                int nb = tile_n0 + warp_n * 64 + ni * 8 + 2 * (lane & 3);
                #pragma unroll
                for (int j = 0; j < 2; j++) {
                    if (!tail || (nb + j) < VTAGS) {
                        ssum[0] += __expf(acc[0][ni][j]);
                        ssum[1] += __expf(acc[0][ni][2 + j]);
                        ssum[2] += __expf(acc[1][ni][j]);
                        ssum[3] += __expf(acc[1][ni][2 + j]);
                    }
                }
            }
        } else if (tile_n0 < VTAGS) {
            float* stage = reinterpret_cast<float*>(smem + SMEM_B_OFF
                                                    + buf * SMEM_B_BYTES);
            const int sh = tail ? 0 : hr;
            #pragma unroll
            for (int h = 0; h < 2; h++) {
                if ((warp_m >> 1) == h) {
                    const int wm = warp_m & 1;
                    #pragma unroll
                    for (int ni = 0; ni < 8; ni++) {
                        int c = warp_n * 64 + ni * 8 + 2 * (lane & 3);
                        #pragma unroll
                        for (int k = 0; k < 4; k++) {
                            int mi = k >> 1, jo = (k & 1) * 2;
                            int lr = wm * 32 + (lane >> 2) + 8 * k;
                            float v0 = __expf(acc[mi][ni][jo + 0]) * inv[k];
                            float v1 = __expf(acc[mi][ni][jo + 1]) * inv[k];
                            stage[lr * STG_STRIDE + ((c - sh) & 127)]     = v0;
                            stage[lr * STG_STRIDE + ((c + 1 - sh) & 127)] = v1;
                        }
                    }
                }
                __syncthreads();
                if (!tail) {
                    #pragma unroll
                    for (int it = 0; it < 8; it++) {
                        int row = it * 8 + wid;
                        int m = tile_m0 + h * 64 + row;
                        float4 v = *reinterpret_cast<float4*>(stage + row * STG_STRIDE
                                                              + 4 * lane);
                        float* p = out + (size_t)m * VTAGS + tile_n0;
                        if (hm == 0) {
                            stg_cs4(p + 4 * lane, v);
                        } else if (lane < 31) {
                            stg_cs4(p + hm + 4 * lane, v);
                        } else {
                            float vv[4] = {v.x, v.y, v.z, v.w};
                            #pragma unroll
                            for (int i = 0; i < 4; i++) {
                                int col = 124 + hm + i;
                                if (col >= 128) col -= 128;
                                stg_cs(p + col, vv[i]);
                            }
                        }
                    }
                } else {
                    #pragma unroll
                    for (int it = 0; it < 8; it++) {
                        int row = it * 8 + wid;
                        int m = tile_m0 + h * 64 + row;
                        #pragma unroll
                        for (int i = 0; i < 4; i++) {
                            int col = lane + 32 * i;
                            int gn = tile_n0 + col;
                            if (gn < VTAGS)
                                stg_cs(out + (size_t)m * VTAGS + gn,
                                       stage[row * STG_STRIDE + col]);
                        }
                    }
                }
                __syncthreads();
            }
        }
    }

    if (!WRITE) {
        #pragma unroll
        for (int o = 1; o <= 2; o <<= 1) {
            #pragma unroll
            for (int k = 0; k < 4; k++)
                ssum[k] += __shfl_xor_sync(0xFFFFFFFFu, ssum[k], o);
        }
        float* red = reinterpret_cast<float*>(smem + SMEM_RED_OFF);
        if ((lane & 3) == 0) {
            #pragma unroll
            for (int k = 0; k < 4; k++)
                red[(r0 + k * 8) * 2 + warp_n] = ssum[k];
        }
        __syncthreads();
        if (tid < 128)
            g_partials[(size_t)blockIdx.x * BATCH + tile_m0 + tid]
                = red[tid * 2] + red[tid * 2 + 1];
    }
}

// ===================== K4: deterministic reduce of partials =================
__global__ void __launch_bounds__(256)
reduce_kernel() {
    int m = blockIdx.x * 8 + (threadIdx.x >> 5);
    int lane = threadIdx.x & 31;
    float s = 0.0f;
    for (int t = lane; t < NGROUPS; t += 32)
        s += g_partials[(size_t)t * BATCH + m];
    #pragma unroll
    for (int o = 16; o > 0; o >>= 1) s += __shfl_xor_sync(0xFFFFFFFFu, s, o);
    if (lane == 0) g_inv_sum[m] = 1.0f / s;
}

// ============================ launch ======================================
extern "C" void kernel_launch(void* const* d_in, const int* in_sizes, int n_in,
                              void* d_out, int out_size)
{
    const int*   v1i  = (const int*)d_in[0];
    const int*   pthi = (const int*)d_in[1];
    const int*   v2i  = (const int*)d_in[2];
    const float* vemb = (const float*)d_in[3];
    const float* pemb = (const float*)d_in[4];
    const float* temb = (const float*)d_in[5];
    const float* Wfc  = (const float*)d_in[6];
    const float* bfc  = (const float*)d_in[7];
    const float* watt = (const float*)d_in[8];
    const float* batt = (const float*)d_in[9];
    float* out = (float*)d_out;

    cudaFuncSetAttribute(fc_kernel,
                         cudaFuncAttributeMaxDynamicSharedMemorySize, SMEM_FC_TOTAL);
    cudaFuncSetAttribute(gemm_softmax_kernel<false>,
                         cudaFuncAttributeMaxDynamicSharedMemorySize, SMEM_K3_TOTAL);
    cudaFuncSetAttribute(gemm_softmax_kernel<true>,
                         cudaFuncAttributeMaxDynamicSharedMemorySize, SMEM_K3_TOTAL);

    gather_kernel<<<BATCH, 128>>>(v1i, pthi, v2i, vemb, pemb, temb, Wfc);
    fc_kernel<<<CTXROWS / 128, 256, SMEM_FC_TOTAL>>>(bfc);
    attention_kernel<<<BATCH, 128>>>(watt, batt);

    dim3 grid(NGROUPS, BATCH / 128);
    gemm_softmax_kernel<false><<<grid, 256, SMEM_K3_TOTAL>>>(nullptr);  // slot 4: profiled
    reduce_kernel<<<BATCH / 8, 256>>>();
    gemm_softmax_kernel<true><<<grid, 256, SMEM_K3_TOTAL>>>(out);
}